// round 7
// baseline (speedup 1.0000x reference)
#include <cuda_runtime.h>
#include <math.h>
#include <stdint.h>

#define L   401
#define B   256
#define LL  (L * L)
#define NCHUNK 8                 // batch chunks in main grid
#define BCHUNK (B / NCHUNK)      // 32 batches per main block = one bit-plane word
#define PW  (3 * L)              // words per batch-word slab: [plane][j]
#define NBLK (NCHUNK * L)        // 3208 main blocks

// ---------------- device globals ----------------
__device__ float    g_bins[L * 32];        // one bin per 128B line: bin d at [d*32]
__device__ float    g_scf[2 * 32];         // [0]=ctcf_num, [32]=within_num (padded lines)
__device__ int      g_sci[2 * 32];         // [0]=nc_sum,   [32]=cnt_within (exact ints)
__device__ uint32_t g_planes[8 * PW];      // [batch_word][plane f/r/c][j], bit = b%32
__device__ unsigned int g_done;

// ---------------- kernel 1: merged prep (planes + analytic counts) ----------------
__global__ __launch_bounds__(512) void prep_kernel(const int* __restrict__ ctcf,
                                                   const float* __restrict__ logits) {
    const int blk = blockIdx.x;
    const int t   = threadIdx.x;

    if (blk < L) {
        // ----- bit-planes: position p = blk, batch b = t -----
        if (t < B) {
            const int p = blk, b = t;
            int o = ctcf[b * L + p];
            float l0 = logits[(b * L + p) * 2 + 0];
            float l1 = logits[(b * L + p) * 2 + 1];
            uint32_t bf = __ballot_sync(0xffffffffu, o == 1);
            uint32_t br = __ballot_sync(0xffffffffu, o == -1);
            uint32_t bc = __ballot_sync(0xffffffffu, l1 > l0);
            if ((b & 31) == 0) {
                int w = b >> 5;
                g_planes[w * PW + 0 * L + p] = bf;
                g_planes[w * PW + 1 * L + p] = br;
                g_planes[w * PW + 2 * L + p] = bc;
            }
        }
    } else {
        // ----- analytic per-batch counts: batch b = blk - L, position p = t -----
        const int b = blk - L;
        const int p = t;
        __shared__ int cnt[5];                 // A, F, R, n1, adjEq
        __shared__ unsigned char compsh[L];
        if (p < 5) cnt[p] = 0;
        __syncthreads();

        int a = 0, f = 0, r = 0, c = 0;
        if (p < L) {
            int o = ctcf[b * L + p];
            a = (o != 0);
            f = (o == 1);
            r = (o == -1);
            float l0 = logits[(b * L + p) * 2 + 0];
            float l1 = logits[(b * L + p) * 2 + 1];
            c = (l1 > l0);                     // argmax, ties -> 0
            compsh[p] = (unsigned char)c;
        }
        __syncthreads();

        int adj = 0;
        if (p < L - 1) adj = (compsh[p] == compsh[p + 1]);

        atomicAdd(&cnt[0], a);
        atomicAdd(&cnt[1], f);
        atomicAdd(&cnt[2], r);
        atomicAdd(&cnt[3], c);
        atomicAdd(&cnt[4], adj);
        __syncthreads();

        if (p == 0) {
            int A = cnt[0], F = cnt[1], R = cnt[2], n1 = cnt[3];
            int n0 = L - n1;
            int nc = A * A - F * R;                            // non_conv count (exact)
            int cw = n0 * n0 + n1 * n1 - L - 2 * cnt[4];       // same & d>=2 (exact)
            atomicAdd(&g_sci[0],  nc);
            atomicAdd(&g_sci[32], cw);
        }
    }
}

// ---------------- kernel 2: streaming pass + last-block finalize ----------------
// block = (batch-word w, row i); thread tid owns j0 = tid and (tid<145) j1 = tid+256.
__global__ __launch_bounds__(256, 8) void main_kernel(const float* __restrict__ cm,
                                                      float* __restrict__ out) {
    const int i   = blockIdx.y;
    const int tid = threadIdx.x;
    const int w   = blockIdx.x;            // batch word (32 batches)

    __shared__ uint32_t sh[PW];            // 4.8 KB slab for this batch-word
    for (int idx = tid; idx < PW; idx += 256)
        sh[idx] = g_planes[w * PW + idx];
    __syncthreads();

    const int  j0   = tid;
    const int  j1   = tid + 256;
    const bool has1 = (j1 < L);
    const int  d0   = abs(i - j0);
    const int  d1   = has1 ? abs(i - j1) : 0;

    const uint32_t fi = sh[i], ri = sh[L + i], ci = sh[2 * L + i];
    const uint32_t ai = fi | ri;

    const uint32_t fj = sh[j0], rj = sh[L + j0], cj = sh[2 * L + j0];
    const uint32_t t10 = ai & (fj | rj) & ~(fi & rj);    // ctcf pair & not convergent
    const uint32_t t20 = (d0 >= 2) ? ~(ci ^ cj) : 0u;    // same compartment & d>=2

    uint32_t t11 = 0u, t21 = 0u;
    if (has1) {
        uint32_t fk = sh[j1], rk = sh[L + j1], ck = sh[2 * L + j1];
        t11 = ai & (fk | rk) & ~(fi & rk);
        t21 = (d1 >= 2) ? ~(ci ^ ck) : 0u;
    }

    float s0 = 0.f, s1 = 0.f, ct = 0.f, wn = 0.f;
    const float* p0 = cm + (size_t)(w * BCHUNK) * LL + (size_t)i * L + j0;

#pragma unroll
    for (int k = 0; k < BCHUNK; ++k) {
        float v = __ldg(p0 + k * LL);
        s0 += v;
        if ((t10 >> k) & 1u) ct += fmaxf(v, 0.f);
        if ((t20 >> k) & 1u) wn += v;
        if (has1) {
            float u = __ldg(p0 + k * LL + 256);
            s1 += u;
            if ((t11 >> k) & 1u) ct += fmaxf(u, 0.f);
            if ((t21 >> k) & 1u) wn += u;
        }
    }

    // one float atomic per thread-slot; bins padded to 1 per 128B line (401 LTS slices)
    atomicAdd(&g_bins[d0 * 32], s0);
    if (has1) atomicAdd(&g_bins[d1 * 32], s1);

    // block-reduce scalars -> one float atomic each (padded lines)
    for (int o = 16; o; o >>= 1) {
        ct += __shfl_down_sync(0xffffffffu, ct, o);
        wn += __shfl_down_sync(0xffffffffu, wn, o);
    }
    __shared__ float red[2][8];
    int wid = tid >> 5, lane = tid & 31;
    if (lane == 0) { red[0][wid] = ct; red[1][wid] = wn; }
    __syncthreads();
    if (tid == 0) {
        float c = 0.f, ww = 0.f;
#pragma unroll
        for (int k = 0; k < 8; ++k) { c += red[0][k]; ww += red[1][k]; }
        atomicAdd(&g_scf[0],  c);
        atomicAdd(&g_scf[32], ww);
    }

    // ---------- last-block finalize ----------
    __threadfence();                       // order this block's atomics device-wide
    __shared__ unsigned int rank_sh;
    if (tid == 0) rank_sh = atomicAdd(&g_done, 1u);
    __syncthreads();
    if (rank_sh != NBLK - 1) return;
    __threadfence();                       // acquire: see all other blocks' atomics

    // 256 threads: bins t0 = tid and t1 = tid + 256 (if < L)
    const int t0 = tid, t1 = tid + 256;
    const bool hb1 = (t1 < L);

    float w0_ = 0.f, ld0 = 0.f, lp0 = 0.f;
    float w1_ = 0.f, ld1 = 0.f, lp1 = 0.f;
    float v4[4] = {0.f, 0.f, 0.f, 0.f};    // n, sum(w*ld), sum(w*lp), masked-sum
    {
        float binv = g_bins[t0 * 32];
        float cntp = (t0 == 0) ? (float)L : 2.0f * (float)(L - t0);
        float mc = binv / (cntp * (float)B);
        bool valid = (t0 >= 2) && isfinite(mc) && (mc > 0.0f);
        w0_ = valid ? 1.f : 0.f;
        ld0 = logf(fmaxf((float)t0, 1.0f));
        lp0 = logf((valid ? mc : 1.0f) + 1e-6f);
        v4[0] += w0_; v4[1] += w0_ * ld0; v4[2] += w0_ * lp0;
        if (t0 >= 2) v4[3] += binv;
    }
    if (hb1) {
        float binv = g_bins[t1 * 32];
        float cntp = 2.0f * (float)(L - t1);
        float mc = binv / (cntp * (float)B);
        bool valid = isfinite(mc) && (mc > 0.0f);   // t1 >= 256 >= 2 always
        w1_ = valid ? 1.f : 0.f;
        ld1 = logf((float)t1);
        lp1 = logf((valid ? mc : 1.0f) + 1e-6f);
        v4[0] += w1_; v4[1] += w1_ * ld1; v4[2] += w1_ * lp1;
        v4[3] += binv;
    }

    // fused 4-wide block reduction (interleaved shfl chains)
    __shared__ float sc4[4][8];
    __shared__ float tot[4];
#pragma unroll
    for (int o = 16; o; o >>= 1)
#pragma unroll
        for (int q = 0; q < 4; ++q) v4[q] += __shfl_down_sync(0xffffffffu, v4[q], o);
    if (lane == 0) { sc4[0][wid] = v4[0]; sc4[1][wid] = v4[1]; sc4[2][wid] = v4[2]; sc4[3][wid] = v4[3]; }
    __syncthreads();
    if (tid < 4) {
        float s = 0.f;
#pragma unroll
        for (int k = 0; k < 8; ++k) s += sc4[tid][k];
        tot[tid] = s;
    }
    __syncthreads();

    float n  = tot[0];
    float ns = fmaxf(n, 1.0f);
    float xm = tot[1] / ns, ym = tot[2] / ns;
    float msk = tot[3];

    float v2[2];
    v2[0] = w0_ * (ld0 - xm) * (lp0 - ym) + w1_ * (ld1 - xm) * (lp1 - ym);
    v2[1] = w0_ * (ld0 - xm) * (ld0 - xm) + w1_ * (ld1 - xm) * (ld1 - xm);
#pragma unroll
    for (int o = 16; o; o >>= 1)
#pragma unroll
        for (int q = 0; q < 2; ++q) v2[q] += __shfl_down_sync(0xffffffffu, v2[q], o);
    if (lane == 0) { sc4[0][wid] = v2[0]; sc4[1][wid] = v2[1]; }
    __syncthreads();
    if (tid == 0) {
        float num = 0.f, den = 0.f;
#pragma unroll
        for (int k = 0; k < 8; ++k) { num += sc4[0][k]; den += sc4[1][k]; }

        // distance decay
        double slope = (double)num / ((double)den + 1e-8);
        double dist  = (n >= 5.0f) ? (slope + 0.85) * (slope + 0.85) : 0.0;
        // ctcf
        double ncs   = (double)g_sci[0];
        double hinge = (double)g_scf[0] / (ncs + 1e-6);
        double ctcfl = (ncs < 1.0) ? 0.0 : hinge;
        // compartment
        double cw      = (double)g_sci[32];
        double cb      = 159600.0 * (double)B - cw;   // (L-1)(L-2) masked pairs per batch
        double within  = (double)g_scf[32] / fmax(cw, 1.0);
        double between = ((double)msk - (double)g_scf[32]) / fmax(cb, 1.0);
        double ratio   = within / (fabs(between) + 1e-6);
        double compl_  = fmax(1.5 - ratio, 0.0);

        out[0] = (float)dist;
        out[1] = (float)ctcfl;
        out[2] = (float)compl_;
        out[3] = (float)(dist + 0.5 * ctcfl + 0.5 * compl_);
    }

    // ---------- reset state for next replay (this block is alone now) ----------
    __syncthreads();
    g_bins[t0 * 32] = 0.f;
    if (hb1) g_bins[t1 * 32] = 0.f;
    if (tid < 2) { g_scf[tid * 32] = 0.f; g_sci[tid * 32] = 0; }
    if (tid == 0) g_done = 0u;
}

// ---------------- launch ----------------
extern "C" void kernel_launch(void* const* d_in, const int* in_sizes, int n_in,
                              void* d_out, int out_size) {
    const float* cm     = (const float*)d_in[0];   // (B, L, L) f32
    const float* logits = (const float*)d_in[1];   // (B, L, 2) f32
    const int*   ctcf   = (const int*)d_in[2];     // (B, L)    i32
    float*       out    = (float*)d_out;           // 4 f32

    prep_kernel<<<L + B, 512>>>(ctcf, logits);
    dim3 grid(NCHUNK, L);
    main_kernel<<<grid, 256>>>(cm, out);
}

// round 8
// speedup vs baseline: 1.0980x; 1.0980x over previous
#include <cuda_runtime.h>
#include <math.h>
#include <stdint.h>

#define L   401
#define B   256
#define LL  (L * L)
#define NCHUNK 8                 // batch words (32 batches each)
#define BCHUNK (B / NCHUNK)      // 32 batches per tile = one bit-plane word
#define PW  (3 * L)              // words per batch-word slab: [plane][j]
#define NTILES (NCHUNK * L)      // 3208 tiles
#define NBLK 888                 // persistent blocks (~148 SM * 6)

// ---------------- device globals ----------------
__device__ float    g_bins[L * 32];        // one bin per 128B line: bin d at [d*32]
__device__ float    g_scf[2 * 32];         // [0]=ctcf_num, [32]=within_num (padded lines)
__device__ int      g_sci[2 * 32];         // [0]=nc_sum,   [32]=cnt_within (exact ints)
__device__ uint32_t g_planes[NCHUNK * PW]; // [batch_word][plane f/r/c][j], bit = b%32
__device__ unsigned int g_done;
__device__ unsigned int g_tile;

// ---------------- kernel 1: merged prep (planes + analytic counts) ----------------
__global__ __launch_bounds__(512) void prep_kernel(const int* __restrict__ ctcf,
                                                   const float* __restrict__ logits) {
    const int blk = blockIdx.x;
    const int t   = threadIdx.x;

    if (blk < L) {
        // ----- bit-planes: position p = blk, batch b = t -----
        if (t < B) {
            const int p = blk, b = t;
            int o = ctcf[b * L + p];
            float l0 = logits[(b * L + p) * 2 + 0];
            float l1 = logits[(b * L + p) * 2 + 1];
            uint32_t bf = __ballot_sync(0xffffffffu, o == 1);
            uint32_t br = __ballot_sync(0xffffffffu, o == -1);
            uint32_t bc = __ballot_sync(0xffffffffu, l1 > l0);
            if ((b & 31) == 0) {
                int w = b >> 5;
                g_planes[w * PW + 0 * L + p] = bf;
                g_planes[w * PW + 1 * L + p] = br;
                g_planes[w * PW + 2 * L + p] = bc;
            }
        }
    } else {
        // ----- analytic per-batch counts: batch b = blk - L, position p = t -----
        const int b = blk - L;
        const int p = t;
        __shared__ int cnt[5];                 // A, F, R, n1, adjEq
        __shared__ unsigned char compsh[L];
        if (p < 5) cnt[p] = 0;
        __syncthreads();

        int a = 0, f = 0, r = 0, c = 0;
        if (p < L) {
            int o = ctcf[b * L + p];
            a = (o != 0);
            f = (o == 1);
            r = (o == -1);
            float l0 = logits[(b * L + p) * 2 + 0];
            float l1 = logits[(b * L + p) * 2 + 1];
            c = (l1 > l0);                     // argmax, ties -> 0
            compsh[p] = (unsigned char)c;
        }
        __syncthreads();

        int adj = 0;
        if (p < L - 1) adj = (compsh[p] == compsh[p + 1]);

        atomicAdd(&cnt[0], a);
        atomicAdd(&cnt[1], f);
        atomicAdd(&cnt[2], r);
        atomicAdd(&cnt[3], c);
        atomicAdd(&cnt[4], adj);
        __syncthreads();

        if (p == 0) {
            int A = cnt[0], F = cnt[1], R = cnt[2], n1 = cnt[3];
            int n0 = L - n1;
            int nc = A * A - F * R;                            // non_conv count (exact)
            int cw = n0 * n0 + n1 * n1 - L - 2 * cnt[4];       // same & d>=2 (exact)
            atomicAdd(&g_sci[0],  nc);
            atomicAdd(&g_sci[32], cw);
        }
    }
}

// ---------------- kernel 2: persistent streaming pass + last-block finalize ----------------
// Tiles (w, i) pulled from g_tile, w-major (slab reuse). Thread tid owns
// j0 = tid and (tid < 145) j1 = tid + 256.
__global__ __launch_bounds__(256) void main_kernel(const float* __restrict__ cm,
                                                   float* __restrict__ out) {
    const int tid = threadIdx.x;
    __shared__ uint32_t sh[PW];            // 4.8 KB plane slab for current batch-word
    __shared__ unsigned int t_sh;

    const int  j0   = tid;
    const int  j1   = tid + 256;
    const bool has1 = (j1 < L);

    float ct = 0.f, wn = 0.f;              // carried across tiles
    int wPrev = -1;

    for (;;) {
        if (tid == 0) t_sh = atomicAdd(&g_tile, 1u);
        __syncthreads();
        const unsigned t = t_sh;
        if (t >= NTILES) break;
        const int w = (int)(t / L);        // batch word, w-major ordering
        const int i = (int)(t - (unsigned)w * L);

        if (w != wPrev) {                  // restage slab (~1-2x per block)
            __syncthreads();
            for (int idx = tid; idx < PW; idx += 256)
                sh[idx] = g_planes[w * PW + idx];
            wPrev = w;
        }
        __syncthreads();

        const int d0 = abs(i - j0);
        const int d1 = has1 ? abs(i - j1) : 0;

        const uint32_t fi = sh[i], ri = sh[L + i], ci = sh[2 * L + i];
        const uint32_t ai = fi | ri;

        const uint32_t fj = sh[j0], rj = sh[L + j0], cj = sh[2 * L + j0];
        const uint32_t t10 = ai & (fj | rj) & ~(fi & rj);    // ctcf pair & not convergent
        const uint32_t t20 = (d0 >= 2) ? ~(ci ^ cj) : 0u;    // same compartment & d>=2

        uint32_t t11 = 0u, t21 = 0u;
        if (has1) {
            uint32_t fk = sh[j1], rk = sh[L + j1], ck = sh[2 * L + j1];
            t11 = ai & (fk | rk) & ~(fi & rk);
            t21 = (d1 >= 2) ? ~(ci ^ ck) : 0u;
        }

        float s0 = 0.f, s1 = 0.f;
        const float* p0 = cm + (size_t)(w * BCHUNK) * LL + (size_t)i * L + j0;

#pragma unroll
        for (int k = 0; k < BCHUNK; ++k) {
            float v = __ldcs(p0 + k * LL);
            s0 += v;
            if ((t10 >> k) & 1u) ct += fmaxf(v, 0.f);
            if ((t20 >> k) & 1u) wn += v;
            if (has1) {
                float u = __ldcs(p0 + k * LL + 256);
                s1 += u;
                if ((t11 >> k) & 1u) ct += fmaxf(u, 0.f);
                if ((t21 >> k) & 1u) wn += u;
            }
        }

        // one float atomic per thread-slot; bins 1 per 128B line (401 LTS slices)
        atomicAdd(&g_bins[d0 * 32], s0);
        if (has1) atomicAdd(&g_bins[d1 * 32], s1);

        __syncthreads();                   // protects t_sh rewrite + slab
    }

    // ---- block-reduce carried scalars once -> one float atomic each ----
    for (int o = 16; o; o >>= 1) {
        ct += __shfl_down_sync(0xffffffffu, ct, o);
        wn += __shfl_down_sync(0xffffffffu, wn, o);
    }
    __shared__ float red[2][8];
    int wid = tid >> 5, lane = tid & 31;
    if (lane == 0) { red[0][wid] = ct; red[1][wid] = wn; }
    __syncthreads();
    if (tid == 0) {
        float c = 0.f, ww = 0.f;
#pragma unroll
        for (int k = 0; k < 8; ++k) { c += red[0][k]; ww += red[1][k]; }
        atomicAdd(&g_scf[0],  c);
        atomicAdd(&g_scf[32], ww);
    }

    // ---------- last-block finalize ----------
    __threadfence();                       // order this block's atomics device-wide
    __shared__ unsigned int rank_sh;
    if (tid == 0) rank_sh = atomicAdd(&g_done, 1u);
    __syncthreads();
    if (rank_sh != NBLK - 1) return;
    __threadfence();                       // acquire: see all other blocks' atomics

    // 256 threads: bins t0 = tid and t1 = tid + 256 (if < L)
    const int t0 = tid, t1 = tid + 256;
    const bool hb1 = (t1 < L);

    float w0_ = 0.f, ld0 = 0.f, lp0 = 0.f;
    float w1_ = 0.f, ld1 = 0.f, lp1 = 0.f;
    float v4[4] = {0.f, 0.f, 0.f, 0.f};    // n, sum(w*ld), sum(w*lp), masked-sum
    {
        float binv = g_bins[t0 * 32];
        float cntp = (t0 == 0) ? (float)L : 2.0f * (float)(L - t0);
        float mc = binv / (cntp * (float)B);
        bool valid = (t0 >= 2) && isfinite(mc) && (mc > 0.0f);
        w0_ = valid ? 1.f : 0.f;
        ld0 = logf(fmaxf((float)t0, 1.0f));
        lp0 = logf((valid ? mc : 1.0f) + 1e-6f);
        v4[0] += w0_; v4[1] += w0_ * ld0; v4[2] += w0_ * lp0;
        if (t0 >= 2) v4[3] += binv;
    }
    if (hb1) {
        float binv = g_bins[t1 * 32];
        float cntp = 2.0f * (float)(L - t1);
        float mc = binv / (cntp * (float)B);
        bool valid = isfinite(mc) && (mc > 0.0f);   // t1 >= 256 >= 2 always
        w1_ = valid ? 1.f : 0.f;
        ld1 = logf((float)t1);
        lp1 = logf((valid ? mc : 1.0f) + 1e-6f);
        v4[0] += w1_; v4[1] += w1_ * ld1; v4[2] += w1_ * lp1;
        v4[3] += binv;
    }

    // fused 4-wide block reduction
    __shared__ float sc4[4][8];
    __shared__ float tot[4];
#pragma unroll
    for (int o = 16; o; o >>= 1)
#pragma unroll
        for (int q = 0; q < 4; ++q) v4[q] += __shfl_down_sync(0xffffffffu, v4[q], o);
    if (lane == 0) { sc4[0][wid] = v4[0]; sc4[1][wid] = v4[1]; sc4[2][wid] = v4[2]; sc4[3][wid] = v4[3]; }
    __syncthreads();
    if (tid < 4) {
        float s = 0.f;
#pragma unroll
        for (int k = 0; k < 8; ++k) s += sc4[tid][k];
        tot[tid] = s;
    }
    __syncthreads();

    float n  = tot[0];
    float ns = fmaxf(n, 1.0f);
    float xm = tot[1] / ns, ym = tot[2] / ns;
    float msk = tot[3];

    float v2[2];
    v2[0] = w0_ * (ld0 - xm) * (lp0 - ym) + w1_ * (ld1 - xm) * (lp1 - ym);
    v2[1] = w0_ * (ld0 - xm) * (ld0 - xm) + w1_ * (ld1 - xm) * (ld1 - xm);
#pragma unroll
    for (int o = 16; o; o >>= 1)
#pragma unroll
        for (int q = 0; q < 2; ++q) v2[q] += __shfl_down_sync(0xffffffffu, v2[q], o);
    if (lane == 0) { sc4[0][wid] = v2[0]; sc4[1][wid] = v2[1]; }
    __syncthreads();
    if (tid == 0) {
        float num = 0.f, den = 0.f;
#pragma unroll
        for (int k = 0; k < 8; ++k) { num += sc4[0][k]; den += sc4[1][k]; }

        // distance decay
        double slope = (double)num / ((double)den + 1e-8);
        double dist  = (n >= 5.0f) ? (slope + 0.85) * (slope + 0.85) : 0.0;
        // ctcf
        double ncs   = (double)g_sci[0];
        double hinge = (double)g_scf[0] / (ncs + 1e-6);
        double ctcfl = (ncs < 1.0) ? 0.0 : hinge;
        // compartment
        double cw      = (double)g_sci[32];
        double cb      = 159600.0 * (double)B - cw;   // (L-1)(L-2) masked pairs per batch
        double within  = (double)g_scf[32] / fmax(cw, 1.0);
        double between = ((double)msk - (double)g_scf[32]) / fmax(cb, 1.0);
        double ratio   = within / (fabs(between) + 1e-6);
        double compl_  = fmax(1.5 - ratio, 0.0);

        out[0] = (float)dist;
        out[1] = (float)ctcfl;
        out[2] = (float)compl_;
        out[3] = (float)(dist + 0.5 * ctcfl + 0.5 * compl_);
    }

    // ---------- reset state for next replay (this block is alone now) ----------
    __syncthreads();
    g_bins[t0 * 32] = 0.f;
    if (hb1) g_bins[t1 * 32] = 0.f;
    if (tid < 2) { g_scf[tid * 32] = 0.f; g_sci[tid * 32] = 0; }
    if (tid == 0) { g_done = 0u; g_tile = 0u; }
}

// ---------------- launch ----------------
extern "C" void kernel_launch(void* const* d_in, const int* in_sizes, int n_in,
                              void* d_out, int out_size) {
    const float* cm     = (const float*)d_in[0];   // (B, L, L) f32
    const float* logits = (const float*)d_in[1];   // (B, L, 2) f32
    const int*   ctcf   = (const int*)d_in[2];     // (B, L)    i32
    float*       out    = (float*)d_out;           // 4 f32

    prep_kernel<<<L + B, 512>>>(ctcf, logits);
    main_kernel<<<NBLK, 256>>>(cm, out);
}

// round 9
// speedup vs baseline: 1.2216x; 1.1126x over previous
#include <cuda_runtime.h>
#include <math.h>
#include <stdint.h>

#define L   401
#define B   256
#define LL  (L * L)
#define NCHUNK 4                 // batch chunks in main grid
#define BCHUNK (B / NCHUNK)      // 64 batches per main block (2 bit-plane words)
#define PW  (3 * L)              // words per batch-word slab: [plane][j]
#define NBLK (NCHUNK * L)        // 1604 main blocks

// ---------------- device globals ----------------
__device__ float    g_bins[L * 32];        // one bin per 128B line: bin d at [d*32]
__device__ float    g_scf[2 * 32];         // [0]=ctcf_num, [32]=within_num (padded lines)
__device__ int      g_sci[2 * 32];         // [0]=nc_sum,   [32]=cnt_within (exact ints)
__device__ uint32_t g_planes[8 * PW];      // [batch_word][plane f/r/c][j], bit = b%32
__device__ unsigned int g_done;

// ---------------- kernel 1: merged prep (planes + analytic counts) ----------------
__global__ __launch_bounds__(512) void prep_kernel(const int* __restrict__ ctcf,
                                                   const float* __restrict__ logits) {
    const int blk = blockIdx.x;
    const int t   = threadIdx.x;

    if (blk < L) {
        // ----- bit-planes: position p = blk, batch b = t -----
        if (t < B) {
            const int p = blk, b = t;
            int o = ctcf[b * L + p];
            float l0 = logits[(b * L + p) * 2 + 0];
            float l1 = logits[(b * L + p) * 2 + 1];
            uint32_t bf = __ballot_sync(0xffffffffu, o == 1);
            uint32_t br = __ballot_sync(0xffffffffu, o == -1);
            uint32_t bc = __ballot_sync(0xffffffffu, l1 > l0);
            if ((b & 31) == 0) {
                int w = b >> 5;
                g_planes[w * PW + 0 * L + p] = bf;
                g_planes[w * PW + 1 * L + p] = br;
                g_planes[w * PW + 2 * L + p] = bc;
            }
        }
    } else {
        // ----- analytic per-batch counts: batch b = blk - L, position p = t -----
        const int b = blk - L;
        const int p = t;
        __shared__ int cnt[5];                 // A, F, R, n1, adjEq
        __shared__ unsigned char compsh[L];
        if (p < 5) cnt[p] = 0;
        __syncthreads();

        int a = 0, f = 0, r = 0, c = 0;
        if (p < L) {
            int o = ctcf[b * L + p];
            a = (o != 0);
            f = (o == 1);
            r = (o == -1);
            float l0 = logits[(b * L + p) * 2 + 0];
            float l1 = logits[(b * L + p) * 2 + 1];
            c = (l1 > l0);                     // argmax, ties -> 0
            compsh[p] = (unsigned char)c;
        }
        __syncthreads();

        int adj = 0;
        if (p < L - 1) adj = (compsh[p] == compsh[p + 1]);

        atomicAdd(&cnt[0], a);
        atomicAdd(&cnt[1], f);
        atomicAdd(&cnt[2], r);
        atomicAdd(&cnt[3], c);
        atomicAdd(&cnt[4], adj);
        __syncthreads();

        if (p == 0) {
            int A = cnt[0], F = cnt[1], R = cnt[2], n1 = cnt[3];
            int n0 = L - n1;
            int nc = A * A - F * R;                            // non_conv count (exact)
            int cw = n0 * n0 + n1 * n1 - L - 2 * cnt[4];       // same & d>=2 (exact)
            atomicAdd(&g_sci[0],  nc);
            atomicAdd(&g_sci[32], cw);
        }
    }
}

// ---------------- kernel 2: streaming pass + last-block finalize ----------------
// block = (batch chunk, row i); thread tid owns j0 = tid and (tid<145) j1 = tid+256.
// Loads are explicitly batched 8-at-a-time per slot to expose MLP to the LSU.
__global__ __launch_bounds__(256) void main_kernel(const float* __restrict__ cm,
                                                   float* __restrict__ out) {
    const int i   = blockIdx.y;
    const int tid = threadIdx.x;
    const int w0  = blockIdx.x * 2;        // first batch-word of this chunk

    __shared__ uint32_t sh[2 * PW];        // 9.6 KB: the 2 batch-words this block needs
    for (int idx = tid; idx < 2 * PW; idx += 256)
        sh[idx] = g_planes[w0 * PW + idx];
    __syncthreads();

    const int  j0   = tid;
    const int  j1   = tid + 256;
    const bool has1 = (j1 < L);
    const int  d0   = abs(i - j0);
    const int  d1   = has1 ? abs(i - j1) : 0;

    float s0 = 0.f, s1 = 0.f, ct = 0.f, wn = 0.f;
    const float* base = cm + (size_t)(blockIdx.x * BCHUNK) * LL + (size_t)i * L + j0;

#pragma unroll
    for (int h = 0; h < 2; ++h) {
        const uint32_t* s = sh + h * PW;
        const uint32_t fi = s[i], ri = s[L + i], ci = s[2 * L + i];
        const uint32_t ai = fi | ri;

        const uint32_t fj = s[j0], rj = s[L + j0], cj = s[2 * L + j0];
        const uint32_t t10 = ai & (fj | rj) & ~(fi & rj);    // ctcf pair & not convergent
        const uint32_t t20 = (d0 >= 2) ? ~(ci ^ cj) : 0u;    // same compartment & d>=2

        uint32_t t11 = 0u, t21 = 0u;
        if (has1) {
            uint32_t fk = s[j1], rk = s[L + j1], ck = s[2 * L + j1];
            t11 = ai & (fk | rk) & ~(fi & rk);
            t21 = (d1 >= 2) ? ~(ci ^ ck) : 0u;
        }

        const float* pb = base + h * 32 * LL;

#pragma unroll
        for (int c4 = 0; c4 < 4; ++c4) {
            // ---- batch-issue 8 (+8) loads before ANY consumption ----
            float v0[8], v1[8];
#pragma unroll
            for (int k = 0; k < 8; ++k)
                v0[k] = __ldcs(pb + (c4 * 8 + k) * LL);
            if (has1) {
#pragma unroll
                for (int k = 0; k < 8; ++k)
                    v1[k] = __ldcs(pb + (c4 * 8 + k) * LL + 256);
            }

            // ---- consume ----
#pragma unroll
            for (int k = 0; k < 8; ++k) {
                const int kk = c4 * 8 + k;
                float v = v0[k];
                s0 += v;
                if ((t10 >> kk) & 1u) ct += fmaxf(v, 0.f);
                if ((t20 >> kk) & 1u) wn += v;
            }
            if (has1) {
#pragma unroll
                for (int k = 0; k < 8; ++k) {
                    const int kk = c4 * 8 + k;
                    float u = v1[k];
                    s1 += u;
                    if ((t11 >> kk) & 1u) ct += fmaxf(u, 0.f);
                    if ((t21 >> kk) & 1u) wn += u;
                }
            }
        }
    }

    // one float atomic per thread-slot; bins padded to 1 per 128B line (401 LTS slices)
    atomicAdd(&g_bins[d0 * 32], s0);
    if (has1) atomicAdd(&g_bins[d1 * 32], s1);

    // block-reduce scalars -> one float atomic each (padded lines)
    for (int o = 16; o; o >>= 1) {
        ct += __shfl_down_sync(0xffffffffu, ct, o);
        wn += __shfl_down_sync(0xffffffffu, wn, o);
    }
    __shared__ float red[2][8];
    int wid = tid >> 5, lane = tid & 31;
    if (lane == 0) { red[0][wid] = ct; red[1][wid] = wn; }
    __syncthreads();
    if (tid == 0) {
        float c = 0.f, ww = 0.f;
#pragma unroll
        for (int k = 0; k < 8; ++k) { c += red[0][k]; ww += red[1][k]; }
        atomicAdd(&g_scf[0],  c);
        atomicAdd(&g_scf[32], ww);
    }

    // ---------- last-block finalize ----------
    __threadfence();                       // order this block's atomics device-wide
    __shared__ unsigned int rank_sh;
    if (tid == 0) rank_sh = atomicAdd(&g_done, 1u);
    __syncthreads();
    if (rank_sh != NBLK - 1) return;
    __threadfence();                       // acquire: see all other blocks' atomics

    // 256 threads: bins t0 = tid and t1 = tid + 256 (if < L)
    const int t0 = tid, t1 = tid + 256;
    const bool hb1 = (t1 < L);

    float w0_ = 0.f, ld0 = 0.f, lp0 = 0.f;
    float w1_ = 0.f, ld1 = 0.f, lp1 = 0.f;
    float v4[4] = {0.f, 0.f, 0.f, 0.f};    // n, sum(w*ld), sum(w*lp), masked-sum
    {
        float binv = g_bins[t0 * 32];
        float cntp = (t0 == 0) ? (float)L : 2.0f * (float)(L - t0);
        float mc = binv / (cntp * (float)B);
        bool valid = (t0 >= 2) && isfinite(mc) && (mc > 0.0f);
        w0_ = valid ? 1.f : 0.f;
        ld0 = logf(fmaxf((float)t0, 1.0f));
        lp0 = logf((valid ? mc : 1.0f) + 1e-6f);
        v4[0] += w0_; v4[1] += w0_ * ld0; v4[2] += w0_ * lp0;
        if (t0 >= 2) v4[3] += binv;
    }
    if (hb1) {
        float binv = g_bins[t1 * 32];
        float cntp = 2.0f * (float)(L - t1);
        float mc = binv / (cntp * (float)B);
        bool valid = isfinite(mc) && (mc > 0.0f);   // t1 >= 256 >= 2 always
        w1_ = valid ? 1.f : 0.f;
        ld1 = logf((float)t1);
        lp1 = logf((valid ? mc : 1.0f) + 1e-6f);
        v4[0] += w1_; v4[1] += w1_ * ld1; v4[2] += w1_ * lp1;
        v4[3] += binv;
    }

    // fused 4-wide block reduction (interleaved shfl chains)
    __shared__ float sc4[4][8];
    __shared__ float tot[4];
#pragma unroll
    for (int o = 16; o; o >>= 1)
#pragma unroll
        for (int q = 0; q < 4; ++q) v4[q] += __shfl_down_sync(0xffffffffu, v4[q], o);
    if (lane == 0) { sc4[0][wid] = v4[0]; sc4[1][wid] = v4[1]; sc4[2][wid] = v4[2]; sc4[3][wid] = v4[3]; }
    __syncthreads();
    if (tid < 4) {
        float s = 0.f;
#pragma unroll
        for (int k = 0; k < 8; ++k) s += sc4[tid][k];
        tot[tid] = s;
    }
    __syncthreads();

    float n  = tot[0];
    float ns = fmaxf(n, 1.0f);
    float xm = tot[1] / ns, ym = tot[2] / ns;
    float msk = tot[3];

    float v2[2];
    v2[0] = w0_ * (ld0 - xm) * (lp0 - ym) + w1_ * (ld1 - xm) * (lp1 - ym);
    v2[1] = w0_ * (ld0 - xm) * (ld0 - xm) + w1_ * (ld1 - xm) * (ld1 - xm);
#pragma unroll
    for (int o = 16; o; o >>= 1)
#pragma unroll
        for (int q = 0; q < 2; ++q) v2[q] += __shfl_down_sync(0xffffffffu, v2[q], o);
    if (lane == 0) { sc4[0][wid] = v2[0]; sc4[1][wid] = v2[1]; }
    __syncthreads();
    if (tid == 0) {
        float num = 0.f, den = 0.f;
#pragma unroll
        for (int k = 0; k < 8; ++k) { num += sc4[0][k]; den += sc4[1][k]; }

        // distance decay
        double slope = (double)num / ((double)den + 1e-8);
        double dist  = (n >= 5.0f) ? (slope + 0.85) * (slope + 0.85) : 0.0;
        // ctcf
        double ncs   = (double)g_sci[0];
        double hinge = (double)g_scf[0] / (ncs + 1e-6);
        double ctcfl = (ncs < 1.0) ? 0.0 : hinge;
        // compartment
        double cw      = (double)g_sci[32];
        double cb      = 159600.0 * (double)B - cw;   // (L-1)(L-2) masked pairs per batch
        double within  = (double)g_scf[32] / fmax(cw, 1.0);
        double between = ((double)msk - (double)g_scf[32]) / fmax(cb, 1.0);
        double ratio   = within / (fabs(between) + 1e-6);
        double compl_  = fmax(1.5 - ratio, 0.0);

        out[0] = (float)dist;
        out[1] = (float)ctcfl;
        out[2] = (float)compl_;
        out[3] = (float)(dist + 0.5 * ctcfl + 0.5 * compl_);
    }

    // ---------- reset state for next replay (this block is alone now) ----------
    __syncthreads();
    g_bins[t0 * 32] = 0.f;
    if (hb1) g_bins[t1 * 32] = 0.f;
    if (tid < 2) { g_scf[tid * 32] = 0.f; g_sci[tid * 32] = 0; }
    if (tid == 0) g_done = 0u;
}

// ---------------- launch ----------------
extern "C" void kernel_launch(void* const* d_in, const int* in_sizes, int n_in,
                              void* d_out, int out_size) {
    const float* cm     = (const float*)d_in[0];   // (B, L, L) f32
    const float* logits = (const float*)d_in[1];   // (B, L, 2) f32
    const int*   ctcf   = (const int*)d_in[2];     // (B, L)    i32
    float*       out    = (float*)d_out;           // 4 f32

    prep_kernel<<<L + B, 512>>>(ctcf, logits);
    dim3 grid(NCHUNK, L);
    main_kernel<<<grid, 256>>>(cm, out);
}